// round 15
// baseline (speedup 1.0000x reference)
#include <cuda_runtime.h>
#include <cuda_fp16.h>
#include <cstdint>

#define BATCH 4
#define SEQ   1370
#define NH    16
#define HD    64
#define HID   1024
#define NTOK  (BATCH * SEQ)   // 5480
#define NELEM ((size_t)BATCH * NH * SEQ * HD)

// Q scale: 1/sqrt(64) * log2(e)  (softmax runs in base-2 domain)
#define QSCALE (0.125f * 1.44269504088896f)

// fp16 input planes (one-shot converted) and projected Q/K/V planes.
__device__ __half g_xh[(size_t)NTOK * HID];
__device__ __half g_wh[(size_t)3 * HID * HID];   // rows: proj*1024 + outch
__device__ __half g_qh[NELEM];
__device__ __half g_kh[NELEM];
__device__ __half g_vh[NELEM];

// ===========================================================================
// Helpers
// ===========================================================================
__device__ __forceinline__ uint32_t smem_u32(const void* p) {
    uint32_t a;
    asm("{ .reg .u64 t; cvta.to.shared.u64 t, %1; cvt.u32.u64 %0, t; }"
        : "=r"(a) : "l"(p));
    return a;
}

#define LDMX4(r, addr) \
    asm volatile("ldmatrix.sync.aligned.m8n8.x4.shared.b16 {%0,%1,%2,%3}, [%4];" \
        : "=r"((r)[0]), "=r"((r)[1]), "=r"((r)[2]), "=r"((r)[3]) : "r"(addr))

#define LDMX4T(r, addr) \
    asm volatile("ldmatrix.sync.aligned.m8n8.x4.trans.shared.b16 {%0,%1,%2,%3}, [%4];" \
        : "=r"((r)[0]), "=r"((r)[1]), "=r"((r)[2]), "=r"((r)[3]) : "r"(addr))

#define LDMX2T(r, addr) \
    asm volatile("ldmatrix.sync.aligned.m8n8.x2.trans.shared.b16 {%0,%1}, [%2];" \
        : "=r"((r)[0]), "=r"((r)[1]) : "r"(addr))

#define MMA16816(d, a, b0, b1) \
    asm volatile("mma.sync.aligned.m16n8k16.row.col.f32.f16.f16.f32 " \
        "{%0,%1,%2,%3}, {%4,%5,%6,%7}, {%8,%9}, {%0,%1,%2,%3};" \
        : "+f"((d)[0]), "+f"((d)[1]), "+f"((d)[2]), "+f"((d)[3]) \
        : "r"((a)[0]), "r"((a)[1]), "r"((a)[2]), "r"((a)[3]), "r"(b0), "r"(b1))

__device__ __forceinline__ uint32_t pack_f16(float lo, float hi) {
    uint32_t r;
    asm("cvt.rn.f16x2.f32 %0, %1, %2;" : "=r"(r) : "f"(hi), "f"(lo));
    return r;
}

__device__ __forceinline__ uint32_t ex2_f16x2(uint32_t x) {
    uint32_t r;
    asm("ex2.approx.f16x2 %0, %1;" : "=r"(r) : "r"(x));
    return r;
}

__device__ __forceinline__ void cp16(uint32_t dst, const void* src, int sz) {
    asm volatile("cp.async.cg.shared.global [%0], [%1], 16, %2;"
                 :: "r"(dst), "l"(src), "r"(sz) : "memory");
}
#define CP_COMMIT() asm volatile("cp.async.commit_group;" ::: "memory")
#define CP_WAIT0()  asm volatile("cp.async.wait_group 0;" ::: "memory")

// ===========================================================================
// Phase 0: one-shot fp32 -> fp16 conversion of X and W (memory-bound, ~9us).
// ===========================================================================
__global__ __launch_bounds__(256)
void convert_half(const float* __restrict__ X,
                  const float* __restrict__ Wq,
                  const float* __restrict__ Wk,
                  const float* __restrict__ Wv)
{
    const size_t nx = (size_t)NTOK * HID / 8;
    const size_t nw = (size_t)3 * HID * HID / 8;
    size_t idx = (size_t)blockIdx.x * 256 + threadIdx.x;
    if (idx >= nx + nw) return;

    const float* src;
    __half* dst;
    if (idx < nx) {
        src = X + idx * 8;
        dst = g_xh + idx * 8;
    } else {
        size_t e = (idx - nx) * 8;
        int proj = (int)(e / (size_t)(HID * HID));
        size_t off = e - (size_t)proj * HID * HID;
        const float* W = (proj == 0) ? Wq : (proj == 1) ? Wk : Wv;
        src = W + off;
        dst = g_wh + e;
    }
    float4 a = *(const float4*)src;
    float4 b = *(const float4*)(src + 4);
    uint4 o;
    o.x = pack_f16(a.x, a.y); o.y = pack_f16(a.z, a.w);
    o.z = pack_f16(b.x, b.y); o.w = pack_f16(b.z, b.w);
    *(uint4*)dst = o;
}

// ===========================================================================
// Phase 1: QKV projection, fp16 mma.sync on pre-converted planes.
// Block tile 128x128, 8 warps (4m x 2n), BK=64, cp.async double buffer.
// ===========================================================================
#define QROWB   144                   // 128B data + 16B pad
#define QTILE   (128 * QROWB)         // 18432
#define QBUF    (2 * QTILE)           // A | B = 36864
#define QK_SMEM (2 * QBUF)            // 73728
#define QCHUNKS (HID / 64)            // 16

__global__ __launch_bounds__(256)
void qkv_mma(const float* __restrict__ bq,
             const float* __restrict__ bk,
             const float* __restrict__ bv)
{
    extern __shared__ char sm[];
    const uint32_t sbase = smem_u32(sm);

    const int tid  = threadIdx.x;
    const int lane = tid & 31;
    const int wid  = tid >> 5;
    const int wm   = wid & 3;
    const int wn   = wid >> 2;

    const int m0   = blockIdx.x * 128;
    const int nb   = blockIdx.y;
    const int proj = nb >> 3;
    const int o0   = (nb & 7) * 128;
    const int wrow0 = proj * 1024 + o0;

    const float* bias = (proj == 0) ? bq : (proj == 1) ? bk : bv;

    float acc[2][8][4];
    #pragma unroll
    for (int mt = 0; mt < 2; mt++)
        #pragma unroll
        for (int nt = 0; nt < 8; nt++)
            #pragma unroll
            for (int r = 0; r < 4; r++) acc[mt][nt][r] = 0.f;

    const uint32_t lmA = (uint32_t)((wm * 32 + (lane & 15)) * QROWB + (lane >> 4) * 16);
    const uint32_t lmB = (uint32_t)((wn * 64 + (lane & 15)) * QROWB + (lane >> 4) * 16);

    auto prefetch = [&](int c, int buf) {
        const int kc = c * 64;
        #pragma unroll
        for (int i = 0; i < 8; i++) {
            int o   = i * 256 + tid;      // 0..2047
            int mat = o >> 10;            // 0=A, 1=B
            int p   = o & 1023;
            int row = p >> 3;
            int seg = p & 7;
            uint32_t dst = sbase + buf * QBUF + mat * QTILE
                         + (uint32_t)(row * QROWB + seg * 16);
            if (mat == 0) {
                int gm = m0 + row;
                cp16(dst, g_xh + (size_t)gm * HID + kc + seg * 8,
                     (gm < NTOK) ? 16 : 0);
            } else {
                cp16(dst, g_wh + (size_t)(wrow0 + row) * HID + kc + seg * 8, 16);
            }
        }
        CP_COMMIT();
    };

    prefetch(0, 0);

    for (int c = 0; c < QCHUNKS; c++) {
        CP_WAIT0();
        __syncthreads();
        if (c + 1 < QCHUNKS) prefetch(c + 1, (c + 1) & 1);

        const uint32_t Ab = sbase + (c & 1) * QBUF;
        const uint32_t Bb = Ab + QTILE;

        #pragma unroll
        for (int ks = 0; ks < 4; ks++) {
            const uint32_t kb = ks * 32;
            uint32_t fA[2][4], fB[4][4];
            #pragma unroll
            for (int mt = 0; mt < 2; mt++)
                LDMX4(fA[mt], Ab + lmA + mt * (16 * QROWB) + kb);
            #pragma unroll
            for (int n2 = 0; n2 < 4; n2++)
                LDMX4(fB[n2], Bb + lmB + n2 * (16 * QROWB) + kb);
            #pragma unroll
            for (int mt = 0; mt < 2; mt++)
                #pragma unroll
                for (int nt = 0; nt < 8; nt++)
                    MMA16816(acc[mt][nt], fA[mt], fB[nt >> 1][nt & 1], fB[nt >> 1][2 + (nt & 1)]);
        }
        __syncthreads();   // ldmatrix reads done before next prefetch's target reuse
    }

    // ---- epilogue: bias add, fp16 round, scatter [B,NH,L,HD] ----
    const int g   = lane >> 2;
    const int tig = lane & 3;
    const int headBase = (o0 + wn * 64) >> 6;
    __half* dp0 = (proj == 0) ? g_qh : (proj == 1) ? g_kh : g_vh;
    const float sc = (proj == 0) ? QSCALE : 1.f;
    #pragma unroll
    for (int mt = 0; mt < 2; mt++) {
        #pragma unroll
        for (int half = 0; half < 2; half++) {
            int gm = m0 + wm * 32 + mt * 16 + g + half * 8;
            if (gm >= NTOK) continue;
            int bb = gm / SEQ;
            int ll = gm - bb * SEQ;
            size_t base = (((size_t)bb * NH + headBase) * SEQ + ll) * HD;
            #pragma unroll
            for (int nt = 0; nt < 8; nt++) {
                int dd = nt * 8 + tig * 2;
                float2 bv = *(const float2*)(bias + o0 + wn * 64 + dd);
                float v0 = (acc[mt][nt][half * 2 + 0] + bv.x) * sc;
                float v1 = (acc[mt][nt][half * 2 + 1] + bv.y) * sc;
                *(uint32_t*)(dp0 + base + dd) = pack_f16(v0, v1);
            }
        }
    }
}

// ===========================================================================
// Phase 2: flash attention, fp16 mma.sync.
// 256 threads, 128 q rows; cp.async double-buffered K/V; softmax via
// ex2.approx.f16x2; l accumulated as a ones-column of the PV MMA.
// ===========================================================================
#define FROWB 144
#define FA_Q  0                          // 128 rows
#define FA_K0 (128 * FROWB)              // 18432
#define FA_V0 (FA_K0 + 64 * FROWB)       // 27648
#define FA_KVSTRIDE (2 * 64 * FROWB)     // 18432 per buffer pair
#define FA_SMEM (FA_K0 + 2 * FA_KVSTRIDE)   // 55296
#define NTILES ((SEQ + 63) / 64)         // 22

__global__ __launch_bounds__(256)
void flash_mma(float* __restrict__ out)
{
    extern __shared__ char sm[];
    const uint32_t sb = smem_u32(sm);

    const int tid  = threadIdx.x;
    const int lane = tid & 31;
    const int w    = tid >> 5;

    const int qt    = blockIdx.x;       // 0..10
    const int bh    = blockIdx.y;       // 0..63
    const int batch = bh >> 4;
    const int head  = bh & 15;
    const __half* Qh = g_qh + (size_t)bh * SEQ * HD;
    const __half* Kh = g_kh + (size_t)bh * SEQ * HD;
    const __half* Vh = g_vh + (size_t)bh * SEQ * HD;
    const int q0 = qt * 128;

    auto prefetch = [&](int kv0, int buf) {
        #pragma unroll
        for (int i = 0; i < 4; i++) {
            int f   = i * 256 + tid;    // 0..1023
            int arr = f >> 9;           // 0=K, 1=V
            int p   = f & 511;
            int row = p >> 3;
            int seg = p & 7;
            int gk  = kv0 + row;
            uint32_t dst = sb + (arr ? FA_V0 : FA_K0) + buf * FA_KVSTRIDE
                         + (uint32_t)(row * FROWB + seg * 16);
            const __half* src = (arr ? Vh : Kh) + (size_t)gk * HD + seg * 8;
            cp16(dst, src, (gk < SEQ) ? 16 : 0);
        }
        CP_COMMIT();
    };

    prefetch(0, 0);

    // Q plane (pre-scaled by 0.125*log2e): 128 rows x 128B.
    #pragma unroll
    for (int i = 0; i < 4; i++) {
        int f   = i * 256 + tid;
        int row = f >> 3;
        int seg = f & 7;
        int gq  = q0 + row;
        const __half* src = Qh + (size_t)gq * HD + seg * 8;
        uint4 v = (gq < SEQ) ? *(const uint4*)src : make_uint4(0u, 0u, 0u, 0u);
        *(uint4*)(sm + FA_Q + row * FROWB + seg * 16) = v;
    }

    // Ones-column init in both V buffers' pad region (cols 64..71):
    // col64 = 1.0h, cols 65..71 = 0. Survives all tiles (loads write 0..127B).
    if (tid < 128) {
        int buf = tid >> 6, row = tid & 63;
        *(uint4*)(sm + FA_V0 + buf * FA_KVSTRIDE + row * FROWB + 128) =
            make_uint4(0x3C00u, 0u, 0u, 0u);
    }

    const uint32_t lmQ  = (uint32_t)((w * 16 + (lane & 15)) * FROWB + (lane >> 4) * 16);
    const uint32_t lmKV = (uint32_t)((lane & 15) * FROWB + (lane >> 4) * 16);
    const uint32_t lmO  = (uint32_t)((lane & 15) * FROWB + 128);   // ones col addr
    const int g   = lane >> 2;
    const int tig = lane & 3;

    float m0v = -1e30f, m1v = -1e30f;
    float O[8][4], Osum[4];
    #pragma unroll
    for (int nt = 0; nt < 8; nt++)
        #pragma unroll
        for (int r = 0; r < 4; r++) O[nt][r] = 0.f;
    #pragma unroll
    for (int r = 0; r < 4; r++) Osum[r] = 0.f;

    for (int t = 0; t < NTILES; t++) {
        const int kv0 = t * 64;
        const int buf = t & 1;

        CP_WAIT0();
        __syncthreads();   // tile data in; all warps done with buffer buf^1
        if (t + 1 < NTILES) prefetch(kv0 + 64, buf ^ 1);

        const uint32_t Kb = sb + FA_K0 + buf * FA_KVSTRIDE;
        const uint32_t Vb = sb + FA_V0 + buf * FA_KVSTRIDE;

        // ---- S = Qh @ Kh^T (log2 domain) ----
        float S[8][4];
        #pragma unroll
        for (int nt = 0; nt < 8; nt++)
            #pragma unroll
            for (int r = 0; r < 4; r++) S[nt][r] = 0.f;

        #pragma unroll
        for (int ks = 0; ks < 4; ks++) {
            uint32_t qh[4];
            LDMX4(qh, sb + FA_Q + lmQ + ks * 32);
            #pragma unroll
            for (int n16 = 0; n16 < 4; n16++) {
                uint32_t kh[4];
                LDMX4(kh, Kb + lmKV + n16 * (16 * FROWB) + ks * 32);
                MMA16816(S[2*n16],   qh, kh[0], kh[2]);
                MMA16816(S[2*n16+1], qh, kh[1], kh[3]);
            }
        }

        // ---- key mask (last tile only) ----
        if (kv0 + 64 > SEQ) {
            #pragma unroll
            for (int nt = 0; nt < 8; nt++)
                #pragma unroll
                for (int e = 0; e < 4; e++)
                    if (kv0 + nt * 8 + tig * 2 + (e & 1) >= SEQ) S[nt][e] = -1e30f;
        }

        // ---- online softmax, base-2 ----
        float mx0 = -1e30f, mx1 = -1e30f;
        #pragma unroll
        for (int nt = 0; nt < 8; nt++) {
            mx0 = fmaxf(mx0, fmaxf(S[nt][0], S[nt][1]));
            mx1 = fmaxf(mx1, fmaxf(S[nt][2], S[nt][3]));
        }
        #pragma unroll
        for (int off = 1; off <= 2; off <<= 1) {
            mx0 = fmaxf(mx0, __shfl_xor_sync(0xffffffffu, mx0, off));
            mx1 = fmaxf(mx1, __shfl_xor_sync(0xffffffffu, mx1, off));
        }
        float mnew0 = fmaxf(m0v, mx0);
        float mnew1 = fmaxf(m1v, mx1);
        float a0 = exp2f(m0v - mnew0);
        float a1 = exp2f(m1v - mnew1);
        m0v = mnew0; m1v = mnew1;

        // P = 2^(S - m) directly in f16x2 (half the MUFU work).
        uint32_t Ph[8][2];
        #pragma unroll
        for (int nt = 0; nt < 8; nt++) {
            Ph[nt][0] = ex2_f16x2(pack_f16(S[nt][0] - mnew0, S[nt][1] - mnew0));
            Ph[nt][1] = ex2_f16x2(pack_f16(S[nt][2] - mnew1, S[nt][3] - mnew1));
        }

        #pragma unroll
        for (int nt = 0; nt < 8; nt++) {
            O[nt][0] *= a0; O[nt][1] *= a0;
            O[nt][2] *= a1; O[nt][3] *= a1;
        }
        Osum[0] *= a0; Osum[1] *= a0;
        Osum[2] *= a1; Osum[3] *= a1;

        // ---- O += Ph @ Vh ; Osum += Ph @ ones-column ----
        #pragma unroll
        for (int ks = 0; ks < 4; ks++) {
            uint32_t aH[4] = {Ph[2*ks][0], Ph[2*ks][1], Ph[2*ks+1][0], Ph[2*ks+1][1]};
            #pragma unroll
            for (int d16 = 0; d16 < 4; d16++) {
                uint32_t vh[4];
                LDMX4T(vh, Vb + lmKV + ks * (16 * FROWB) + d16 * 32);
                MMA16816(O[2*d16],   aH, vh[0], vh[1]);
                MMA16816(O[2*d16+1], aH, vh[2], vh[3]);
            }
            uint32_t ov[2];
            LDMX2T(ov, Vb + lmO + ks * (16 * FROWB));
            MMA16816(Osum, aH, ov[0], ov[1]);
        }
    }

    // ---- epilogue: l lives in Osum col 64 (quad-leader lanes) ----
    float l0 = __shfl_sync(0xffffffffu, Osum[0], lane & 28);
    float l1 = __shfl_sync(0xffffffffu, Osum[2], lane & 28);
    const float inv0 = 1.f / l0;
    const float inv1 = 1.f / l1;
    const int r0 = q0 + w * 16 + g;
    const int r1 = r0 + 8;
    #pragma unroll
    for (int nt = 0; nt < 8; nt++) {
        int dd = head * HD + nt * 8 + tig * 2;
        if (r0 < SEQ) {
            float2 o = make_float2(O[nt][0] * inv0, O[nt][1] * inv0);
            *(float2*)(out + ((size_t)batch * SEQ + r0) * HID + dd) = o;
        }
        if (r1 < SEQ) {
            float2 o = make_float2(O[nt][2] * inv1, O[nt][3] * inv1);
            *(float2*)(out + ((size_t)batch * SEQ + r1) * HID + dd) = o;
        }
    }
}

// ---------------------------------------------------------------------------
// Launch
// ---------------------------------------------------------------------------
extern "C" void kernel_launch(void* const* d_in, const int* in_sizes, int n_in,
                              void* d_out, int out_size)
{
    const float* X  = (const float*)d_in[0];
    const float* Wq = (const float*)d_in[1];
    const float* bq = (const float*)d_in[2];
    const float* Wk = (const float*)d_in[3];
    const float* bk = (const float*)d_in[4];
    const float* Wv = (const float*)d_in[5];
    const float* bv = (const float*)d_in[6];
    float* out = (float*)d_out;

    cudaFuncSetAttribute(qkv_mma,   cudaFuncAttributeMaxDynamicSharedMemorySize, QK_SMEM);
    cudaFuncSetAttribute(flash_mma, cudaFuncAttributeMaxDynamicSharedMemorySize, FA_SMEM);

    const size_t nconv = (size_t)NTOK * HID / 8 + (size_t)3 * HID * HID / 8;
    convert_half<<<(unsigned)((nconv + 255) / 256), 256>>>(X, Wq, Wk, Wv);

    dim3 g1((NTOK + 127) / 128, 24);                 // 43 x 24
    qkv_mma<<<g1, 256, QK_SMEM>>>(bq, bk, bv);

    dim3 g2((SEQ + 127) / 128, BATCH * NH);          // 11 x 64
    flash_mma<<<g2, 256, FA_SMEM>>>(out);
}

// round 16
// speedup vs baseline: 1.2964x; 1.2964x over previous
#include <cuda_runtime.h>
#include <cuda_fp16.h>
#include <cstdint>

#define BATCH 4
#define SEQ   1370
#define NH    16
#define HD    64
#define HID   1024
#define NTOK  (BATCH * SEQ)   // 5480
#define NELEM ((size_t)BATCH * NH * SEQ * HD)

// Q scale: 1/sqrt(64) * log2(e)  (softmax runs in base-2 domain)
#define QSCALE (0.125f * 1.44269504088896f)

// Scratch: projected Q/K/V as fp16, [B, NH, L, HD] layout.
__device__ __half g_qh[NELEM];
__device__ __half g_kh[NELEM];
__device__ __half g_vh[NELEM];

// ===========================================================================
// Helpers
// ===========================================================================
__device__ __forceinline__ uint32_t smem_u32(const void* p) {
    uint32_t a;
    asm("{ .reg .u64 t; cvta.to.shared.u64 t, %1; cvt.u32.u64 %0, t; }"
        : "=r"(a) : "l"(p));
    return a;
}

#define LDMX4(r, addr) \
    asm volatile("ldmatrix.sync.aligned.m8n8.x4.shared.b16 {%0,%1,%2,%3}, [%4];" \
        : "=r"((r)[0]), "=r"((r)[1]), "=r"((r)[2]), "=r"((r)[3]) : "r"(addr))

#define LDMX4T(r, addr) \
    asm volatile("ldmatrix.sync.aligned.m8n8.x4.trans.shared.b16 {%0,%1,%2,%3}, [%4];" \
        : "=r"((r)[0]), "=r"((r)[1]), "=r"((r)[2]), "=r"((r)[3]) : "r"(addr))

#define LDMX2T(r, addr) \
    asm volatile("ldmatrix.sync.aligned.m8n8.x2.trans.shared.b16 {%0,%1}, [%2];" \
        : "=r"((r)[0]), "=r"((r)[1]) : "r"(addr))

#define MMA16816(d, a, b0, b1) \
    asm volatile("mma.sync.aligned.m16n8k16.row.col.f32.f16.f16.f32 " \
        "{%0,%1,%2,%3}, {%4,%5,%6,%7}, {%8,%9}, {%0,%1,%2,%3};" \
        : "+f"((d)[0]), "+f"((d)[1]), "+f"((d)[2]), "+f"((d)[3]) \
        : "r"((a)[0]), "r"((a)[1]), "r"((a)[2]), "r"((a)[3]), "r"(b0), "r"(b1))

__device__ __forceinline__ uint32_t pack_f16(float lo, float hi) {
    uint32_t r;
    asm("cvt.rn.f16x2.f32 %0, %1, %2;" : "=r"(r) : "f"(hi), "f"(lo));
    return r;
}

__device__ __forceinline__ uint32_t ex2_f16x2(uint32_t x) {
    uint32_t r;
    asm("ex2.approx.f16x2 %0, %1;" : "=r"(r) : "r"(x));
    return r;
}

// fp32x4 -> rounded fp16, 8B to one plane.
__device__ __forceinline__ void round_sts(char* hp, uint32_t off, float4 v) {
    *(uint2*)(hp + off) = make_uint2(pack_f16(v.x, v.y), pack_f16(v.z, v.w));
}

// ===========================================================================
// Phase 1: QKV projection (IDENTICAL to R14 — measured ~145us).
// Pure fp16 mma.sync: Y = rn(X) @ rn(W)^T + b. Block 128x128, BK=32,
// register-staged fp32 loads, double-buffered smem.
// ===========================================================================
#define QBK     32
#define QROWB   80
#define QTILE   (128 * QROWB)        // 10240
#define QBUF    (2 * QTILE)          // Ah | Bh = 20480
#define QK_SMEM (2 * QBUF)           // 40960
#define QCHUNKS (HID / QBK)

__global__ __launch_bounds__(256)
void qkv_mma(const float* __restrict__ X,
             const float* __restrict__ Wq, const float* __restrict__ bq,
             const float* __restrict__ Wk, const float* __restrict__ bk,
             const float* __restrict__ Wv, const float* __restrict__ bv)
{
    extern __shared__ char sm[];
    const uint32_t sbase = smem_u32(sm);

    const int tid  = threadIdx.x;
    const int lane = tid & 31;
    const int wid  = tid >> 5;
    const int wm   = wid & 3;
    const int wn   = wid >> 2;

    const int m0   = blockIdx.x * 128;
    const int nb   = blockIdx.y;
    const int proj = nb >> 3;
    const int o0   = (nb & 7) * 128;

    const float* W    = (proj == 0) ? Wq : (proj == 1) ? Wk : Wv;
    const float* bias = (proj == 0) ? bq : (proj == 1) ? bk : bv;

    float acc[2][8][4];
    #pragma unroll
    for (int mt = 0; mt < 2; mt++)
        #pragma unroll
        for (int nt = 0; nt < 8; nt++)
            #pragma unroll
            for (int r = 0; r < 4; r++) acc[mt][nt][r] = 0.f;

    float4 stA[4], stB[4];
    const int ldRow = tid >> 3;
    const int ldC   = (tid & 7) << 2;

    const uint32_t lmA = (uint32_t)((wm * 32 + (lane & 15)) * QROWB + (lane >> 4) * 16);
    const uint32_t lmB = (uint32_t)((wn * 64 + (lane & 15)) * QROWB + (lane >> 4) * 16);

    #pragma unroll
    for (int i = 0; i < 4; i++) {
        int row = ldRow + i * 32;
        int gm  = m0 + row;
        stA[i] = (gm < NTOK) ? *(const float4*)(X + (size_t)gm * HID + ldC)
                             : make_float4(0.f, 0.f, 0.f, 0.f);
        stB[i] = *(const float4*)(W + (size_t)(o0 + row) * HID + ldC);
    }
    {
        char* Ah = sm; char* Bh = sm + QTILE;
        #pragma unroll
        for (int i = 0; i < 4; i++) {
            uint32_t off = (uint32_t)((ldRow + i * 32) * QROWB + ldC * 2);
            round_sts(Ah, off, stA[i]);
            round_sts(Bh, off, stB[i]);
        }
    }
    __syncthreads();

    for (int c = 0; c < QCHUNKS; c++) {
        if (c + 1 < QCHUNKS) {
            int kc = (c + 1) * QBK;
            #pragma unroll
            for (int i = 0; i < 4; i++) {
                int row = ldRow + i * 32;
                int gm  = m0 + row;
                stA[i] = (gm < NTOK) ? *(const float4*)(X + (size_t)gm * HID + kc + ldC)
                                     : make_float4(0.f, 0.f, 0.f, 0.f);
                stB[i] = *(const float4*)(W + (size_t)(o0 + row) * HID + kc + ldC);
            }
        }

        const uint32_t Ahb = sbase + (c & 1) * QBUF;
        const uint32_t Bhb = Ahb + QTILE;

        #pragma unroll
        for (int kk = 0; kk < 2; kk++) {
            const uint32_t kb = kk * 32;
            uint32_t fAh[2][4], fB[4][4];
            #pragma unroll
            for (int mt = 0; mt < 2; mt++)
                LDMX4(fAh[mt], Ahb + lmA + mt * (16 * QROWB) + kb);
            #pragma unroll
            for (int n2 = 0; n2 < 4; n2++)
                LDMX4(fB[n2], Bhb + lmB + n2 * (16 * QROWB) + kb);
            #pragma unroll
            for (int mt = 0; mt < 2; mt++)
                #pragma unroll
                for (int nt = 0; nt < 8; nt++)
                    MMA16816(acc[mt][nt], fAh[mt], fB[nt >> 1][nt & 1], fB[nt >> 1][2 + (nt & 1)]);
        }

        if (c + 1 < QCHUNKS) {
            char* Ah = sm + ((c + 1) & 1) * QBUF;
            char* Bh = Ah + QTILE;
            #pragma unroll
            for (int i = 0; i < 4; i++) {
                uint32_t off = (uint32_t)((ldRow + i * 32) * QROWB + ldC * 2);
                round_sts(Ah, off, stA[i]);
                round_sts(Bh, off, stB[i]);
            }
        }
        __syncthreads();
    }

    // ---- epilogue: bias add, fp16 round, scatter [B,NH,L,HD] ----
    const int g   = lane >> 2;
    const int tig = lane & 3;
    const int headBase = (o0 + wn * 64) >> 6;
    __half* dp0 = (proj == 0) ? g_qh : (proj == 1) ? g_kh : g_vh;
    const float sc = (proj == 0) ? QSCALE : 1.f;
    #pragma unroll
    for (int mt = 0; mt < 2; mt++) {
        #pragma unroll
        for (int half = 0; half < 2; half++) {
            int gm = m0 + wm * 32 + mt * 16 + g + half * 8;
            if (gm >= NTOK) continue;
            int bb = gm / SEQ;
            int ll = gm - bb * SEQ;
            size_t base = (((size_t)bb * NH + headBase) * SEQ + ll) * HD;
            #pragma unroll
            for (int nt = 0; nt < 8; nt++) {
                int dd = nt * 8 + tig * 2;
                float2 bv = *(const float2*)(bias + o0 + wn * 64 + dd);
                float v0 = (acc[mt][nt][half * 2 + 0] + bv.x) * sc;
                float v1 = (acc[mt][nt][half * 2 + 1] + bv.y) * sc;
                *(uint32_t*)(dp0 + base + dd) = pack_f16(v0, v1);
            }
        }
    }
}

// ===========================================================================
// Phase 2: flash attention — R14 structure (plain loads, 2 barriers/tile),
// with ONLY the softmax reworked:
//   - P = ex2.approx.f16x2 on packed (S - m) pairs  (half the MUFU work)
//   - l accumulated as a ones-column of the PV MMA  (no fp32 sums/shuffles)
// ===========================================================================
#define FROWB 144
#define FA_QH 0
#define FA_KH (128 * FROWB)                 // 18432
#define FA_VH (FA_KH + 64 * FROWB)          // 27648
#define FA_SMEM (FA_VH + 64 * FROWB)        // 36864

__global__ __launch_bounds__(256)
void flash_mma(float* __restrict__ out)
{
    extern __shared__ char sm[];
    const uint32_t sb = smem_u32(sm);

    const int tid  = threadIdx.x;
    const int lane = tid & 31;
    const int w    = tid >> 5;

    const int qt    = blockIdx.x;       // 0..10
    const int bh    = blockIdx.y;       // 0..63
    const int batch = bh >> 4;
    const int head  = bh & 15;
    const __half* Qh = g_qh + (size_t)bh * SEQ * HD;
    const __half* Kh = g_kh + (size_t)bh * SEQ * HD;
    const __half* Vh = g_vh + (size_t)bh * SEQ * HD;
    const int q0 = qt * 128;

    // Load Q plane (fp16, pre-scaled): 128 rows x 128B.
    #pragma unroll
    for (int i = 0; i < 4; i++) {
        int f   = i * 256 + tid;            // 0..1023 16B-chunk ids
        int row = f >> 3;
        int seg = f & 7;
        int gq  = q0 + row;
        const __half* src = Qh + (size_t)gq * HD + seg * 8;
        uint4 v = (gq < SEQ) ? *(const uint4*)src : make_uint4(0u, 0u, 0u, 0u);
        *(uint4*)(sm + FA_QH + row * FROWB + seg * 16) = v;
    }

    // Ones-column init in V pad region (cols 64..71): col64=1.0h, rest 0.
    // Tile loads write only bytes 0..127 of each row, so the pad persists.
    if (tid < 64) {
        *(uint4*)(sm + FA_VH + tid * FROWB + 128) = make_uint4(0x3C00u, 0u, 0u, 0u);
    }

    const uint32_t lmQ  = (uint32_t)((w * 16 + (lane & 15)) * FROWB + (lane >> 4) * 16);
    const uint32_t lmKV = (uint32_t)((lane & 15) * FROWB + (lane >> 4) * 16);
    const uint32_t lmO  = (uint32_t)((lane & 15) * FROWB + 128);   // ones column
    const int g   = lane >> 2;
    const int tig = lane & 3;

    float m0v = -1e30f, m1v = -1e30f;
    float O[8][4], Osum[4];
    #pragma unroll
    for (int nt = 0; nt < 8; nt++)
        #pragma unroll
        for (int r = 0; r < 4; r++) O[nt][r] = 0.f;
    #pragma unroll
    for (int r = 0; r < 4; r++) Osum[r] = 0.f;

    for (int kv0 = 0; kv0 < SEQ; kv0 += 64) {
        __syncthreads();   // prior tile's ldmatrix done (and Q/ones stores, iter 0)

        // Load K, V tiles (fp16 native): 2 x 64 rows x 128B.
        #pragma unroll
        for (int i = 0; i < 4; i++) {
            int f   = i * 256 + tid;        // 0..1023
            int arr = f >> 9;               // 0=K, 1=V
            int p   = f & 511;
            int row = p >> 3;
            int seg = p & 7;
            int gk  = kv0 + row;
            const __half* src = (arr ? Vh : Kh) + (size_t)gk * HD + seg * 8;
            uint4 v = (gk < SEQ) ? *(const uint4*)src : make_uint4(0u, 0u, 0u, 0u);
            *(uint4*)(sm + (arr ? FA_VH : FA_KH) + row * FROWB + seg * 16) = v;
        }
        __syncthreads();

        // ---- S = Qh @ Kh^T (log2 domain) ----
        float S[8][4];
        #pragma unroll
        for (int nt = 0; nt < 8; nt++)
            #pragma unroll
            for (int r = 0; r < 4; r++) S[nt][r] = 0.f;

        #pragma unroll
        for (int ks = 0; ks < 4; ks++) {
            uint32_t qh[4];
            LDMX4(qh, sb + FA_QH + lmQ + ks * 32);
            #pragma unroll
            for (int n16 = 0; n16 < 4; n16++) {
                uint32_t kh[4];
                LDMX4(kh, sb + FA_KH + lmKV + n16 * (16 * FROWB) + ks * 32);
                MMA16816(S[2*n16],   qh, kh[0], kh[2]);
                MMA16816(S[2*n16+1], qh, kh[1], kh[3]);
            }
        }

        // ---- key mask (last tile only) ----
        if (kv0 + 64 > SEQ) {
            #pragma unroll
            for (int nt = 0; nt < 8; nt++)
                #pragma unroll
                for (int e = 0; e < 4; e++)
                    if (kv0 + nt * 8 + tig * 2 + (e & 1) >= SEQ) S[nt][e] = -1e30f;
        }

        // ---- online softmax, base-2 (rows g / g+8; quad reduction) ----
        float mx0 = -1e30f, mx1 = -1e30f;
        #pragma unroll
        for (int nt = 0; nt < 8; nt++) {
            mx0 = fmaxf(mx0, fmaxf(S[nt][0], S[nt][1]));
            mx1 = fmaxf(mx1, fmaxf(S[nt][2], S[nt][3]));
        }
        #pragma unroll
        for (int off = 1; off <= 2; off <<= 1) {
            mx0 = fmaxf(mx0, __shfl_xor_sync(0xffffffffu, mx0, off));
            mx1 = fmaxf(mx1, __shfl_xor_sync(0xffffffffu, mx1, off));
        }
        float mnew0 = fmaxf(m0v, mx0);
        float mnew1 = fmaxf(m1v, mx1);
        float a0 = exp2f(m0v - mnew0);
        float a1 = exp2f(m1v - mnew1);
        m0v = mnew0; m1v = mnew1;

        // P = 2^(S - m) in f16x2 (masked cols: -inf -> 0).
        uint32_t Ph[8][2];
        #pragma unroll
        for (int nt = 0; nt < 8; nt++) {
            Ph[nt][0] = ex2_f16x2(pack_f16(S[nt][0] - mnew0, S[nt][1] - mnew0));
            Ph[nt][1] = ex2_f16x2(pack_f16(S[nt][2] - mnew1, S[nt][3] - mnew1));
        }

        #pragma unroll
        for (int nt = 0; nt < 8; nt++) {
            O[nt][0] *= a0; O[nt][1] *= a0;
            O[nt][2] *= a1; O[nt][3] *= a1;
        }
        Osum[0] *= a0; Osum[1] *= a0;
        Osum[2] *= a1; Osum[3] *= a1;

        // ---- O += Ph @ Vh ; Osum += Ph @ ones-column ----
        #pragma unroll
        for (int ks = 0; ks < 4; ks++) {
            uint32_t aH[4] = {Ph[2*ks][0], Ph[2*ks][1], Ph[2*ks+1][0], Ph[2*ks+1][1]};
            #pragma unroll
            for (int d16 = 0; d16 < 4; d16++) {
                uint32_t vh[4];
                LDMX4T(vh, sb + FA_VH + lmKV + ks * (16 * FROWB) + d16 * 32);
                MMA16816(O[2*d16],   aH, vh[0], vh[1]);
                MMA16816(O[2*d16+1], aH, vh[2], vh[3]);
            }
            uint32_t ov[2];
            LDMX2T(ov, sb + FA_VH + lmO + ks * (16 * FROWB));
            MMA16816(Osum, aH, ov[0], ov[1]);
        }
    }

    // ---- epilogue: l lives in Osum col 64 (tig==0 lanes); broadcast ----
    float l0 = __shfl_sync(0xffffffffu, Osum[0], lane & 28);
    float l1 = __shfl_sync(0xffffffffu, Osum[2], lane & 28);
    const float inv0 = 1.f / l0;
    const float inv1 = 1.f / l1;
    const int r0 = q0 + w * 16 + g;
    const int r1 = r0 + 8;
    #pragma unroll
    for (int nt = 0; nt < 8; nt++) {
        int dd = head * HD + nt * 8 + tig * 2;
        if (r0 < SEQ) {
            float2 o = make_float2(O[nt][0] * inv0, O[nt][1] * inv0);
            *(float2*)(out + ((size_t)batch * SEQ + r0) * HID + dd) = o;
        }
        if (r1 < SEQ) {
            float2 o = make_float2(O[nt][2] * inv1, O[nt][3] * inv1);
            *(float2*)(out + ((size_t)batch * SEQ + r1) * HID + dd) = o;
        }
    }
}

// ---------------------------------------------------------------------------
// Launch
// ---------------------------------------------------------------------------
extern "C" void kernel_launch(void* const* d_in, const int* in_sizes, int n_in,
                              void* d_out, int out_size)
{
    const float* X  = (const float*)d_in[0];
    const float* Wq = (const float*)d_in[1];
    const float* bq = (const float*)d_in[2];
    const float* Wk = (const float*)d_in[3];
    const float* bk = (const float*)d_in[4];
    const float* Wv = (const float*)d_in[5];
    const float* bv = (const float*)d_in[6];
    float* out = (float*)d_out;

    cudaFuncSetAttribute(qkv_mma,   cudaFuncAttributeMaxDynamicSharedMemorySize, QK_SMEM);
    cudaFuncSetAttribute(flash_mma, cudaFuncAttributeMaxDynamicSharedMemorySize, FA_SMEM);

    dim3 g1((NTOK + 127) / 128, 24);                 // 43 x 24
    qkv_mma<<<g1, 256, QK_SMEM>>>(X, Wq, bq, Wk, bk, Wv, bv);

    dim3 g2((SEQ + 127) / 128, BATCH * NH);          // 11 x 64
    flash_mma<<<g2, 256, FA_SMEM>>>(out);
}

// round 17
// speedup vs baseline: 1.3510x; 1.0422x over previous
#include <cuda_runtime.h>
#include <cuda_fp16.h>
#include <cstdint>

#define BATCH 4
#define SEQ   1370
#define NH    16
#define HD    64
#define HID   1024
#define NTOK  (BATCH * SEQ)   // 5480
#define NELEM ((size_t)BATCH * NH * SEQ * HD)

// Q scale: 1/sqrt(64) * log2(e)  (softmax runs in base-2 domain)
#define QSCALE (0.125f * 1.44269504088896f)

// One-shot fp16 copies of the inputs, + projected Q/K/V planes.
__device__ __half g_xh[(size_t)NTOK * HID];
__device__ __half g_wh[(size_t)3 * HID * HID];   // rows: proj*1024 + outch
__device__ __half g_qh[NELEM];
__device__ __half g_kh[NELEM];
__device__ __half g_vh[NELEM];

// ===========================================================================
// Helpers
// ===========================================================================
__device__ __forceinline__ uint32_t smem_u32(const void* p) {
    uint32_t a;
    asm("{ .reg .u64 t; cvta.to.shared.u64 t, %1; cvt.u32.u64 %0, t; }"
        : "=r"(a) : "l"(p));
    return a;
}

#define LDMX4(r, addr) \
    asm volatile("ldmatrix.sync.aligned.m8n8.x4.shared.b16 {%0,%1,%2,%3}, [%4];" \
        : "=r"((r)[0]), "=r"((r)[1]), "=r"((r)[2]), "=r"((r)[3]) : "r"(addr))

#define LDMX4T(r, addr) \
    asm volatile("ldmatrix.sync.aligned.m8n8.x4.trans.shared.b16 {%0,%1,%2,%3}, [%4];" \
        : "=r"((r)[0]), "=r"((r)[1]), "=r"((r)[2]), "=r"((r)[3]) : "r"(addr))

#define LDMX2T(r, addr) \
    asm volatile("ldmatrix.sync.aligned.m8n8.x2.trans.shared.b16 {%0,%1}, [%2];" \
        : "=r"((r)[0]), "=r"((r)[1]) : "r"(addr))

#define MMA16816(d, a, b0, b1) \
    asm volatile("mma.sync.aligned.m16n8k16.row.col.f32.f16.f16.f32 " \
        "{%0,%1,%2,%3}, {%4,%5,%6,%7}, {%8,%9}, {%0,%1,%2,%3};" \
        : "+f"((d)[0]), "+f"((d)[1]), "+f"((d)[2]), "+f"((d)[3]) \
        : "r"((a)[0]), "r"((a)[1]), "r"((a)[2]), "r"((a)[3]), "r"(b0), "r"(b1))

__device__ __forceinline__ uint32_t pack_f16(float lo, float hi) {
    uint32_t r;
    asm("cvt.rn.f16x2.f32 %0, %1, %2;" : "=r"(r) : "f"(hi), "f"(lo));
    return r;
}

__device__ __forceinline__ uint32_t ex2_f16x2(uint32_t x) {
    uint32_t r;
    asm("ex2.approx.f16x2 %0, %1;" : "=r"(r) : "r"(x));
    return r;
}

// ===========================================================================
// Phase 0: one-shot fp32 -> fp16 conversion of X and W (~11us, memory-bound).
// ===========================================================================
__global__ __launch_bounds__(256)
void convert_half(const float* __restrict__ X,
                  const float* __restrict__ Wq,
                  const float* __restrict__ Wk,
                  const float* __restrict__ Wv)
{
    const size_t nx = (size_t)NTOK * HID / 8;
    const size_t nw = (size_t)3 * HID * HID / 8;
    size_t idx = (size_t)blockIdx.x * 256 + threadIdx.x;
    if (idx >= nx + nw) return;

    const float* src;
    __half* dst;
    if (idx < nx) {
        src = X + idx * 8;
        dst = g_xh + idx * 8;
    } else {
        size_t e = (idx - nx) * 8;
        int proj = (int)(e / (size_t)(HID * HID));
        size_t off = e - (size_t)proj * HID * HID;
        const float* W = (proj == 0) ? Wq : (proj == 1) ? Wk : Wv;
        src = W + off;
        dst = g_wh + e;
    }
    float4 a = *(const float4*)src;
    float4 b = *(const float4*)(src + 4);
    uint4 o;
    o.x = pack_f16(a.x, a.y); o.y = pack_f16(a.z, a.w);
    o.z = pack_f16(b.x, b.y); o.w = pack_f16(b.z, b.w);
    *(uint4*)dst = o;
}

// ===========================================================================
// Phase 1: QKV projection — R14 structure exactly (BK=32, QROWB=80,
// register-staged loads, double-buffered smem, same barriers/epilogue),
// but reading the pre-converted fp16 planes (half the L2 bytes, no cvt).
// ===========================================================================
#define QBK     32
#define QROWB   80
#define QTILE   (128 * QROWB)        // 10240
#define QBUF    (2 * QTILE)          // Ah | Bh = 20480
#define QK_SMEM (2 * QBUF)           // 40960
#define QCHUNKS (HID / QBK)

__global__ __launch_bounds__(256)
void qkv_mma(const float* __restrict__ bq,
             const float* __restrict__ bk,
             const float* __restrict__ bv)
{
    extern __shared__ char sm[];
    const uint32_t sbase = smem_u32(sm);

    const int tid  = threadIdx.x;
    const int lane = tid & 31;
    const int wid  = tid >> 5;
    const int wm   = wid & 3;
    const int wn   = wid >> 2;

    const int m0   = blockIdx.x * 128;
    const int nb   = blockIdx.y;
    const int proj = nb >> 3;
    const int o0   = (nb & 7) * 128;
    const int wrow0 = proj * 1024 + o0;

    const float* bias = (proj == 0) ? bq : (proj == 1) ? bk : bv;

    float acc[2][8][4];
    #pragma unroll
    for (int mt = 0; mt < 2; mt++)
        #pragma unroll
        for (int nt = 0; nt < 8; nt++)
            #pragma unroll
            for (int r = 0; r < 4; r++) acc[mt][nt][r] = 0.f;

    uint2 stA[4], stB[4];
    const int ldRow = tid >> 3;            // 0..31 (x4 via i*32)
    const int ldC   = (tid & 7) << 2;      // half-element offset, 4 halves/thread

    const uint32_t lmA = (uint32_t)((wm * 32 + (lane & 15)) * QROWB + (lane >> 4) * 16);
    const uint32_t lmB = (uint32_t)((wn * 64 + (lane & 15)) * QROWB + (lane >> 4) * 16);

    #pragma unroll
    for (int i = 0; i < 4; i++) {
        int row = ldRow + i * 32;
        int gm  = m0 + row;
        stA[i] = (gm < NTOK) ? *(const uint2*)(g_xh + (size_t)gm * HID + ldC)
                             : make_uint2(0u, 0u);
        stB[i] = *(const uint2*)(g_wh + (size_t)(wrow0 + row) * HID + ldC);
    }
    {
        char* Ah = sm; char* Bh = sm + QTILE;
        #pragma unroll
        for (int i = 0; i < 4; i++) {
            uint32_t off = (uint32_t)((ldRow + i * 32) * QROWB + ldC * 2);
            *(uint2*)(Ah + off) = stA[i];
            *(uint2*)(Bh + off) = stB[i];
        }
    }
    __syncthreads();

    for (int c = 0; c < QCHUNKS; c++) {
        if (c + 1 < QCHUNKS) {
            int kc = (c + 1) * QBK;
            #pragma unroll
            for (int i = 0; i < 4; i++) {
                int row = ldRow + i * 32;
                int gm  = m0 + row;
                stA[i] = (gm < NTOK) ? *(const uint2*)(g_xh + (size_t)gm * HID + kc + ldC)
                                     : make_uint2(0u, 0u);
                stB[i] = *(const uint2*)(g_wh + (size_t)(wrow0 + row) * HID + kc + ldC);
            }
        }

        const uint32_t Ahb = sbase + (c & 1) * QBUF;
        const uint32_t Bhb = Ahb + QTILE;

        #pragma unroll
        for (int kk = 0; kk < 2; kk++) {
            const uint32_t kb = kk * 32;
            uint32_t fAh[2][4], fB[4][4];
            #pragma unroll
            for (int mt = 0; mt < 2; mt++)
                LDMX4(fAh[mt], Ahb + lmA + mt * (16 * QROWB) + kb);
            #pragma unroll
            for (int n2 = 0; n2 < 4; n2++)
                LDMX4(fB[n2], Bhb + lmB + n2 * (16 * QROWB) + kb);
            #pragma unroll
            for (int mt = 0; mt < 2; mt++)
                #pragma unroll
                for (int nt = 0; nt < 8; nt++)
                    MMA16816(acc[mt][nt], fAh[mt], fB[nt >> 1][nt & 1], fB[nt >> 1][2 + (nt & 1)]);
        }

        if (c + 1 < QCHUNKS) {
            char* Ah = sm + ((c + 1) & 1) * QBUF;
            char* Bh = Ah + QTILE;
            #pragma unroll
            for (int i = 0; i < 4; i++) {
                uint32_t off = (uint32_t)((ldRow + i * 32) * QROWB + ldC * 2);
                *(uint2*)(Ah + off) = stA[i];
                *(uint2*)(Bh + off) = stB[i];
            }
        }
        __syncthreads();
    }

    // ---- epilogue: bias add, fp16 round, scatter [B,NH,L,HD] ----
    const int g   = lane >> 2;
    const int tig = lane & 3;
    const int headBase = (o0 + wn * 64) >> 6;
    __half* dp0 = (proj == 0) ? g_qh : (proj == 1) ? g_kh : g_vh;
    const float sc = (proj == 0) ? QSCALE : 1.f;
    #pragma unroll
    for (int mt = 0; mt < 2; mt++) {
        #pragma unroll
        for (int half = 0; half < 2; half++) {
            int gm = m0 + wm * 32 + mt * 16 + g + half * 8;
            if (gm >= NTOK) continue;
            int bb = gm / SEQ;
            int ll = gm - bb * SEQ;
            size_t base = (((size_t)bb * NH + headBase) * SEQ + ll) * HD;
            #pragma unroll
            for (int nt = 0; nt < 8; nt++) {
                int dd = nt * 8 + tig * 2;
                float2 bv = *(const float2*)(bias + o0 + wn * 64 + dd);
                float v0 = (acc[mt][nt][half * 2 + 0] + bv.x) * sc;
                float v1 = (acc[mt][nt][half * 2 + 1] + bv.y) * sc;
                *(uint32_t*)(dp0 + base + dd) = pack_f16(v0, v1);
            }
        }
    }
}

// ===========================================================================
// Phase 2: flash attention — IDENTICAL to R16 (measured 126us).
// ===========================================================================
#define FROWB 144
#define FA_QH 0
#define FA_KH (128 * FROWB)                 // 18432
#define FA_VH (FA_KH + 64 * FROWB)          // 27648
#define FA_SMEM (FA_VH + 64 * FROWB)        // 36864

__global__ __launch_bounds__(256)
void flash_mma(float* __restrict__ out)
{
    extern __shared__ char sm[];
    const uint32_t sb = smem_u32(sm);

    const int tid  = threadIdx.x;
    const int lane = tid & 31;
    const int w    = tid >> 5;

    const int qt    = blockIdx.x;       // 0..10
    const int bh    = blockIdx.y;       // 0..63
    const int batch = bh >> 4;
    const int head  = bh & 15;
    const __half* Qh = g_qh + (size_t)bh * SEQ * HD;
    const __half* Kh = g_kh + (size_t)bh * SEQ * HD;
    const __half* Vh = g_vh + (size_t)bh * SEQ * HD;
    const int q0 = qt * 128;

    // Load Q plane (fp16, pre-scaled): 128 rows x 128B.
    #pragma unroll
    for (int i = 0; i < 4; i++) {
        int f   = i * 256 + tid;            // 0..1023 16B-chunk ids
        int row = f >> 3;
        int seg = f & 7;
        int gq  = q0 + row;
        const __half* src = Qh + (size_t)gq * HD + seg * 8;
        uint4 v = (gq < SEQ) ? *(const uint4*)src : make_uint4(0u, 0u, 0u, 0u);
        *(uint4*)(sm + FA_QH + row * FROWB + seg * 16) = v;
    }

    // Ones-column init in V pad region (cols 64..71): col64=1.0h, rest 0.
    if (tid < 64) {
        *(uint4*)(sm + FA_VH + tid * FROWB + 128) = make_uint4(0x3C00u, 0u, 0u, 0u);
    }

    const uint32_t lmQ  = (uint32_t)((w * 16 + (lane & 15)) * FROWB + (lane >> 4) * 16);
    const uint32_t lmKV = (uint32_t)((lane & 15) * FROWB + (lane >> 4) * 16);
    const uint32_t lmO  = (uint32_t)((lane & 15) * FROWB + 128);   // ones column
    const int g   = lane >> 2;
    const int tig = lane & 3;

    float m0v = -1e30f, m1v = -1e30f;
    float O[8][4], Osum[4];
    #pragma unroll
    for (int nt = 0; nt < 8; nt++)
        #pragma unroll
        for (int r = 0; r < 4; r++) O[nt][r] = 0.f;
    #pragma unroll
    for (int r = 0; r < 4; r++) Osum[r] = 0.f;

    for (int kv0 = 0; kv0 < SEQ; kv0 += 64) {
        __syncthreads();

        #pragma unroll
        for (int i = 0; i < 4; i++) {
            int f   = i * 256 + tid;
            int arr = f >> 9;               // 0=K, 1=V
            int p   = f & 511;
            int row = p >> 3;
            int seg = p & 7;
            int gk  = kv0 + row;
            const __half* src = (arr ? Vh : Kh) + (size_t)gk * HD + seg * 8;
            uint4 v = (gk < SEQ) ? *(const uint4*)src : make_uint4(0u, 0u, 0u, 0u);
            *(uint4*)(sm + (arr ? FA_VH : FA_KH) + row * FROWB + seg * 16) = v;
        }
        __syncthreads();

        // ---- S = Qh @ Kh^T (log2 domain) ----
        float S[8][4];
        #pragma unroll
        for (int nt = 0; nt < 8; nt++)
            #pragma unroll
            for (int r = 0; r < 4; r++) S[nt][r] = 0.f;

        #pragma unroll
        for (int ks = 0; ks < 4; ks++) {
            uint32_t qh[4];
            LDMX4(qh, sb + FA_QH + lmQ + ks * 32);
            #pragma unroll
            for (int n16 = 0; n16 < 4; n16++) {
                uint32_t kh[4];
                LDMX4(kh, sb + FA_KH + lmKV + n16 * (16 * FROWB) + ks * 32);
                MMA16816(S[2*n16],   qh, kh[0], kh[2]);
                MMA16816(S[2*n16+1], qh, kh[1], kh[3]);
            }
        }

        if (kv0 + 64 > SEQ) {
            #pragma unroll
            for (int nt = 0; nt < 8; nt++)
                #pragma unroll
                for (int e = 0; e < 4; e++)
                    if (kv0 + nt * 8 + tig * 2 + (e & 1) >= SEQ) S[nt][e] = -1e30f;
        }

        float mx0 = -1e30f, mx1 = -1e30f;
        #pragma unroll
        for (int nt = 0; nt < 8; nt++) {
            mx0 = fmaxf(mx0, fmaxf(S[nt][0], S[nt][1]));
            mx1 = fmaxf(mx1, fmaxf(S[nt][2], S[nt][3]));
        }
        #pragma unroll
        for (int off = 1; off <= 2; off <<= 1) {
            mx0 = fmaxf(mx0, __shfl_xor_sync(0xffffffffu, mx0, off));
            mx1 = fmaxf(mx1, __shfl_xor_sync(0xffffffffu, mx1, off));
        }
        float mnew0 = fmaxf(m0v, mx0);
        float mnew1 = fmaxf(m1v, mx1);
        float a0 = exp2f(m0v - mnew0);
        float a1 = exp2f(m1v - mnew1);
        m0v = mnew0; m1v = mnew1;

        uint32_t Ph[8][2];
        #pragma unroll
        for (int nt = 0; nt < 8; nt++) {
            Ph[nt][0] = ex2_f16x2(pack_f16(S[nt][0] - mnew0, S[nt][1] - mnew0));
            Ph[nt][1] = ex2_f16x2(pack_f16(S[nt][2] - mnew1, S[nt][3] - mnew1));
        }

        #pragma unroll
        for (int nt = 0; nt < 8; nt++) {
            O[nt][0] *= a0; O[nt][1] *= a0;
            O[nt][2] *= a1; O[nt][3] *= a1;
        }
        Osum[0] *= a0; Osum[1] *= a0;
        Osum[2] *= a1; Osum[3] *= a1;

        #pragma unroll
        for (int ks = 0; ks < 4; ks++) {
            uint32_t aH[4] = {Ph[2*ks][0], Ph[2*ks][1], Ph[2*ks+1][0], Ph[2*ks+1][1]};
            #pragma unroll
            for (int d16 = 0; d16 < 4; d16++) {
                uint32_t vh[4];
                LDMX4T(vh, sb + FA_VH + lmKV + ks * (16 * FROWB) + d16 * 32);
                MMA16816(O[2*d16],   aH, vh[0], vh[1]);
                MMA16816(O[2*d16+1], aH, vh[2], vh[3]);
            }
            uint32_t ov[2];
            LDMX2T(ov, sb + FA_VH + lmO + ks * (16 * FROWB));
            MMA16816(Osum, aH, ov[0], ov[1]);
        }
    }

    float l0 = __shfl_sync(0xffffffffu, Osum[0], lane & 28);
    float l1 = __shfl_sync(0xffffffffu, Osum[2], lane & 28);
    const float inv0 = 1.f / l0;
    const float inv1 = 1.f / l1;
    const int r0 = q0 + w * 16 + g;
    const int r1 = r0 + 8;
    #pragma unroll
    for (int nt = 0; nt < 8; nt++) {
        int dd = head * HD + nt * 8 + tig * 2;
        if (r0 < SEQ) {
            float2 o = make_float2(O[nt][0] * inv0, O[nt][1] * inv0);
            *(float2*)(out + ((size_t)batch * SEQ + r0) * HID + dd) = o;
        }
        if (r1 < SEQ) {
            float2 o = make_float2(O[nt][2] * inv1, O[nt][3] * inv1);
            *(float2*)(out + ((size_t)batch * SEQ + r1) * HID + dd) = o;
        }
    }
}

// ---------------------------------------------------------------------------
// Launch
// ---------------------------------------------------------------------------
extern "C" void kernel_launch(void* const* d_in, const int* in_sizes, int n_in,
                              void* d_out, int out_size)
{
    const float* X  = (const float*)d_in[0];
    const float* Wq = (const float*)d_in[1];
    const float* bq = (const float*)d_in[2];
    const float* Wk = (const float*)d_in[3];
    const float* bk = (const float*)d_in[4];
    const float* Wv = (const float*)d_in[5];
    const float* bv = (const float*)d_in[6];
    float* out = (float*)d_out;

    cudaFuncSetAttribute(qkv_mma,   cudaFuncAttributeMaxDynamicSharedMemorySize, QK_SMEM);
    cudaFuncSetAttribute(flash_mma, cudaFuncAttributeMaxDynamicSharedMemorySize, FA_SMEM);

    const size_t nconv = (size_t)NTOK * HID / 8 + (size_t)3 * HID * HID / 8;
    convert_half<<<(unsigned)((nconv + 255) / 256), 256>>>(X, Wq, Wk, Wv);

    dim3 g1((NTOK + 127) / 128, 24);                 // 43 x 24
    qkv_mma<<<g1, 256, QK_SMEM>>>(bq, bk, bv);

    dim3 g2((SEQ + 127) / 128, BATCH * NH);          // 11 x 64
    flash_mma<<<g2, 256, FA_SMEM>>>(out);
}